// round 8
// baseline (speedup 1.0000x reference)
#include <cuda_runtime.h>

#ifndef B_DIM
#define B_DIM 8
#define N_DIM 8192
#define M_DIM 128
#endif

constexpr int WARPS_PER_CTA = 4;
constexpr int PTS_PER_WARP  = 8;   // 4 iterations x 2 concurrent points
constexpr int PTS_PER_CTA   = WARPS_PER_CTA * PTS_PER_WARP;  // 32
constexpr int THREADS       = WARPS_PER_CTA * 32;            // 128

typedef unsigned long long u64;

// ---------- packed f32x2 helpers (Blackwell) ----------
__device__ __forceinline__ u64 pack2(float lo, float hi) {
    u64 r; asm("mov.b64 %0, {%1,%2};" : "=l"(r) : "f"(lo), "f"(hi)); return r;
}
__device__ __forceinline__ u64 splat2(float v) { return pack2(v, v); }
__device__ __forceinline__ void unpack2(u64 v, float& lo, float& hi) {
    asm("mov.b64 {%0,%1}, %2;" : "=f"(lo), "=f"(hi) : "l"(v));
}
__device__ __forceinline__ u64 fma2(u64 a, u64 b, u64 c) {
    u64 d; asm("fma.rn.f32x2 %0, %1, %2, %3;" : "=l"(d) : "l"(a), "l"(b), "l"(c)); return d;
}
__device__ __forceinline__ u64 mul2(u64 a, u64 b) {
    u64 d; asm("mul.rn.f32x2 %0, %1, %2;" : "=l"(d) : "l"(a), "l"(b)); return d;
}
__device__ __forceinline__ u64 add2(u64 a, u64 b) {
    u64 d; asm("add.rn.f32x2 %0, %1, %2;" : "=l"(d) : "l"(a), "l"(b)); return d;
}
__device__ __forceinline__ float sqrt_approx(float x) {
    float r; asm("sqrt.approx.f32 %0, %1;" : "=f"(r) : "f"(x)); return r;
}
__device__ __forceinline__ float rcp_approx(float x) {
    float r; asm("rcp.approx.f32 %0, %1;" : "=f"(r) : "f"(x)); return r;
}

struct Consts {
    u64 aS[4];        // splat(W1[j][0])
    u64 w2S[4][4];    // splat(W2[i][j])
    u64 b2S[4];
    u64 w3S[4];
    u64 b3S;
    u64 k02;          // (0.2, 0.2)
};

// leaky on an element-pair: unpack is register-pair aliasing (free in SASS)
__device__ __forceinline__ u64 leaky_p(u64 z, u64 k02) {
    const u64 t = mul2(z, k02);
    float z0, z1, t0, t1;
    unpack2(z, z0, z1); unpack2(t, t0, t1);
    return pack2(fmaxf(z0, t0), fmaxf(z1, t1));
}

// MLP for one element-pair; weights are loop-invariant splats, zero per-call MOVs
__device__ __forceinline__ u64 mlp_pair(u64 f, const u64 cp[4], const Consts& C) {
    const u64 h0 = leaky_p(fma2(C.aS[0], f, cp[0]), C.k02);
    const u64 h1 = leaky_p(fma2(C.aS[1], f, cp[1]), C.k02);
    const u64 h2 = leaky_p(fma2(C.aS[2], f, cp[2]), C.k02);
    const u64 h3 = leaky_p(fma2(C.aS[3], f, cp[3]), C.k02);
    const u64 g0 = leaky_p(fma2(C.w2S[0][0], h0, fma2(C.w2S[0][1], h1,
                           fma2(C.w2S[0][2], h2, fma2(C.w2S[0][3], h3, C.b2S[0])))), C.k02);
    const u64 g1 = leaky_p(fma2(C.w2S[1][0], h0, fma2(C.w2S[1][1], h1,
                           fma2(C.w2S[1][2], h2, fma2(C.w2S[1][3], h3, C.b2S[1])))), C.k02);
    const u64 g2 = leaky_p(fma2(C.w2S[2][0], h0, fma2(C.w2S[2][1], h1,
                           fma2(C.w2S[2][2], h2, fma2(C.w2S[2][3], h3, C.b2S[2])))), C.k02);
    const u64 g3 = leaky_p(fma2(C.w2S[3][0], h0, fma2(C.w2S[3][1], h1,
                           fma2(C.w2S[3][2], h2, fma2(C.w2S[3][3], h3, C.b2S[3])))), C.k02);
    return fma2(C.w3S[0], g0, fma2(C.w3S[1], g1,
           fma2(C.w3S[2], g2, fma2(C.w3S[3], g3, C.b3S))));
}

__global__ void __launch_bounds__(THREADS)
featuration_kernel(const float* __restrict__ xyz,   // [B,3,N]
                   const float* __restrict__ V,     // [B,M,3]
                   const float* __restrict__ W1,    // [4,4]
                   const float* __restrict__ b1,    // [4]
                   const float* __restrict__ W2,    // [4,4]
                   const float* __restrict__ b2,    // [4]
                   const float* __restrict__ W3,    // [1,4]
                   const float* __restrict__ b3,    // [1]
                   float* __restrict__ out)         // [B,N,M]
{
    __shared__ float4 Vs[M_DIM];
    __shared__ float4 Cs[M_DIM];

    const int b   = blockIdx.y;
    const int tid = threadIdx.x;

    // THREADS == 128 == M_DIM: every thread inits one m
    {
        const float vx = __ldg(&V[(b * M_DIM + tid) * 3 + 0]);
        const float vy = __ldg(&V[(b * M_DIM + tid) * 3 + 1]);
        const float vz = __ldg(&V[(b * M_DIM + tid) * 3 + 2]);
        Vs[tid] = make_float4(vx, vy, vz, 0.0f);
        float4 c;
        c.x = fmaf(__ldg(&W1[1]),  vx, fmaf(__ldg(&W1[2]),  vy, fmaf(__ldg(&W1[3]),  vz, __ldg(&b1[0]))));
        c.y = fmaf(__ldg(&W1[5]),  vx, fmaf(__ldg(&W1[6]),  vy, fmaf(__ldg(&W1[7]),  vz, __ldg(&b1[1]))));
        c.z = fmaf(__ldg(&W1[9]),  vx, fmaf(__ldg(&W1[10]), vy, fmaf(__ldg(&W1[11]), vz, __ldg(&b1[2]))));
        c.w = fmaf(__ldg(&W1[13]), vx, fmaf(__ldg(&W1[14]), vy, fmaf(__ldg(&W1[15]), vz, __ldg(&b1[3]))));
        Cs[tid] = c;
    }

    // loop-invariant splat weights
    Consts C;
#pragma unroll
    for (int j = 0; j < 4; j++) {
        C.aS[j]  = splat2(__ldg(&W1[4 * j]));
#pragma unroll
        for (int i = 0; i < 4; i++) C.w2S[j][i] = splat2(__ldg(&W2[4 * j + i]));
        C.b2S[j] = splat2(__ldg(&b2[j]));
        C.w3S[j] = splat2(__ldg(&W3[j]));
    }
    C.b3S = splat2(__ldg(&b3[0]));
    C.k02 = splat2(0.2f);

    __syncthreads();

    const int warp = tid >> 5;
    const int lane = tid & 31;
    const int half = lane >> 4;     // which of the 2 concurrent points
    const int sub  = lane & 15;     // position within the 16-lane point group
    const int m0   = 8 * sub;       // lane owns m = m0 .. m0+7 (4 element-pairs)

    // per-lane negated-V pairs and layer-1 constant pairs (packed across adjacent m)
    u64 nvx[4], nvy[4], nvz[4];
    u64 cp[4][4];
#pragma unroll
    for (int k = 0; k < 4; k++) {
        const float4 ve = Vs[m0 + 2 * k];
        const float4 vo = Vs[m0 + 2 * k + 1];
        nvx[k] = pack2(-ve.x, -vo.x);
        nvy[k] = pack2(-ve.y, -vo.y);
        nvz[k] = pack2(-ve.z, -vo.z);
        const float4 ce = Cs[m0 + 2 * k];
        const float4 co = Cs[m0 + 2 * k + 1];
        cp[k][0] = pack2(ce.x, co.x);
        cp[k][1] = pack2(ce.y, co.y);
        cp[k][2] = pack2(ce.z, co.z);
        cp[k][3] = pack2(ce.w, co.w);
    }

    const float* xb = xyz + (size_t)b * 3 * N_DIM;
    float* outb = out + (size_t)b * N_DIM * M_DIM;

    const int n_base = blockIdx.x * PTS_PER_CTA + warp * PTS_PER_WARP;

#pragma unroll
    for (int p = 0; p < PTS_PER_WARP / 2; p++) {
        const int n = n_base + 2 * p + half;   // half-warp owns its own point
        const float px = __ldg(&xb[n]);
        const float py = __ldg(&xb[N_DIM + n]);
        const float pz = __ldg(&xb[2 * N_DIM + n]);
        const u64 pxs = splat2(px), pys = splat2(py), pzs = splat2(pz);

        // squared distances for the lane's 4 m-pairs
        u64 s[4];
#pragma unroll
        for (int k = 0; k < 4; k++) {
            const u64 dx = add2(pxs, nvx[k]);
            const u64 dy = add2(pys, nvy[k]);
            const u64 dz = add2(pzs, nvz[k]);
            s[k] = fma2(dx, dx, fma2(dy, dy, mul2(dz, dz)));
        }

        // local fold over 8 values (squared; sqrt is monotone)
        float s0, s1, s2, s3, s4, s5, s6, s7;
        unpack2(s[0], s0, s1); unpack2(s[1], s2, s3);
        unpack2(s[2], s4, s5); unpack2(s[3], s6, s7);
        float mns = fminf(fminf(fminf(s0, s1), fminf(s2, s3)),
                          fminf(fminf(s4, s5), fminf(s6, s7)));
        float mxs = fmaxf(fmaxf(fmaxf(s0, s1), fmaxf(s2, s3)),
                          fmaxf(fmaxf(s4, s5), fmaxf(s6, s7)));

        // 4-level butterfly within the 16-lane group (offsets never cross halves)
#pragma unroll
        for (int off = 8; off > 0; off >>= 1) {
            mns = fminf(mns, __shfl_xor_sync(0xFFFFFFFFu, mns, off));
            mxs = fmaxf(mxs, __shfl_xor_sync(0xFFFFFFFFu, mxs, off));
        }

        const float mn = sqrt_approx(mns);
        const float mx = sqrt_approx(mxs);
        const float denom = mx - mn;
        const float inv = (denom > 0.0f) ? rcp_approx(denom) : 0.0f;
        const float nmninv = -mn * inv;
        const u64 invS = splat2(inv), nmS = splat2(nmninv);

        // per-pair: d = sqrt(s), f = d*inv + nm, MLP
        u64 o[4];
        {
            const u64 d0p = pack2(sqrt_approx(s0), sqrt_approx(s1));
            o[0] = mlp_pair(fma2(d0p, invS, nmS), cp[0], C);
            const u64 d1p = pack2(sqrt_approx(s2), sqrt_approx(s3));
            o[1] = mlp_pair(fma2(d1p, invS, nmS), cp[1], C);
            const u64 d2p = pack2(sqrt_approx(s4), sqrt_approx(s5));
            o[2] = mlp_pair(fma2(d2p, invS, nmS), cp[2], C);
            const u64 d3p = pack2(sqrt_approx(s6), sqrt_approx(s7));
            o[3] = mlp_pair(fma2(d3p, invS, nmS), cp[3], C);
        }

        // store 8 contiguous floats (two 16B stores); half-warps write adjacent rows
        float* dst = outb + (size_t)n * M_DIM + m0;
        reinterpret_cast<ulonglong2*>(dst)[0] = make_ulonglong2(o[0], o[1]);
        reinterpret_cast<ulonglong2*>(dst + 4)[0] = make_ulonglong2(o[2], o[3]);
    }
}

extern "C" void kernel_launch(void* const* d_in, const int* in_sizes, int n_in,
                              void* d_out, int out_size) {
    const float* xyz = (const float*)d_in[0];
    const float* V   = (const float*)d_in[1];
    const float* W1  = (const float*)d_in[2];
    const float* b1  = (const float*)d_in[3];
    const float* W2  = (const float*)d_in[4];
    const float* b2  = (const float*)d_in[5];
    const float* W3  = (const float*)d_in[6];
    const float* b3  = (const float*)d_in[7];
    float* out = (float*)d_out;

    dim3 grid(N_DIM / PTS_PER_CTA, B_DIM);  // (256, 8)
    featuration_kernel<<<grid, THREADS>>>(xyz, V, W1, b1, W2, b2, W3, b3, out);
}